// round 1
// baseline (speedup 1.0000x reference)
#include <cuda_runtime.h>
#include <math.h>

// GPT-2 small forward: B=4, T=1024, E=768, H=12, HD=64, V=50304, L=12
#define Bn   4
#define Tn   1024
#define En   768
#define Hn   12
#define HDn  64
#define Vn   50304
#define Ln   12
#define Mrows 4096           // B*T
#define E3   2304            // 3*E
#define E4   3072            // 4*E

// ---------------- scratch (device globals; no allocation allowed) -------------
__device__ float g_x[Mrows * En];                 // residual stream
__device__ float g_h[Mrows * En];                 // ln output
__device__ float g_qkv[Mrows * E3];               // qkv projection
__device__ float g_y[Mrows * En];                 // attention output
__device__ float g_fc[Mrows * E4];                // mlp hidden
__device__ float g_att[(size_t)Bn * Hn * Tn * Tn]; // attention matrix (201MB)
__device__ float g_rowloss[Mrows];

// ---------------- embedding ---------------------------------------------------
__global__ void k_embed(const int* __restrict__ idx,
                        const float* __restrict__ wte,
                        const float* __restrict__ wpe) {
    int row = blockIdx.x;            // 0..4095  (b*T + t)
    int t = row & (Tn - 1);
    int tok = idx[row];
    const float* src = wte + (size_t)tok * En;
    const float* pos = wpe + (size_t)t * En;
    float* dst = g_x + (size_t)row * En;
    for (int e = threadIdx.x; e < En; e += blockDim.x)
        dst[e] = src[e] + pos[e];
}

// ---------------- layernorm ----------------------------------------------------
__global__ void k_ln(const float* __restrict__ in, float* __restrict__ out,
                     const float* __restrict__ g, const float* __restrict__ b) {
    int row = blockIdx.x;
    int tid = threadIdx.x;
    const float* x = in + (size_t)row * En;
    float s = 0.f, ss = 0.f;
    for (int e = tid; e < En; e += 256) { float v = x[e]; s += v; ss += v * v; }
    __shared__ float sh[512];
    sh[tid] = s; sh[256 + tid] = ss;
    __syncthreads();
    for (int st = 128; st > 0; st >>= 1) {
        if (tid < st) { sh[tid] += sh[tid + st]; sh[256 + tid] += sh[256 + tid + st]; }
        __syncthreads();
    }
    float mean = sh[0] * (1.f / En);
    float var  = sh[256] * (1.f / En) - mean * mean;
    float rstd = rsqrtf(var + 1e-5f);
    float* o = out + (size_t)row * En;
    for (int e = tid; e < En; e += 256)
        o[e] = (x[e] - mean) * rstd * g[e] + b[e];
}

// ---------------- GEMM: C[M,N] = A[M,K] @ W[N,K]^T + bias + residual ----------
// 64x64 tile, BK=16, 256 threads, 4x4 per thread. M%64==0, N%64==0, K%16==0.
__global__ void k_gemm(const float* __restrict__ A, const float* __restrict__ W,
                       const float* __restrict__ bias, const float* __restrict__ res,
                       float* __restrict__ C, int M, int N, int K) {
    __shared__ __align__(16) float As[16][64];
    __shared__ __align__(16) float Bs[16][64];
    const int tid = threadIdx.x;
    const int m0 = blockIdx.y << 6, n0 = blockIdx.x << 6;
    const int ty = tid >> 4, tx = tid & 15;
    const int lr = tid >> 2;              // 0..63
    const int lc = (tid & 3) << 2;        // 0,4,8,12
    const float* Ap = A + (size_t)(m0 + lr) * K + lc;
    const float* Wp = W + (size_t)(n0 + lr) * K + lc;
    float acc[4][4] = {};
    for (int k0 = 0; k0 < K; k0 += 16) {
        float4 av = *(const float4*)(Ap + k0);
        float4 bv = *(const float4*)(Wp + k0);
        As[lc + 0][lr] = av.x; As[lc + 1][lr] = av.y;
        As[lc + 2][lr] = av.z; As[lc + 3][lr] = av.w;
        Bs[lc + 0][lr] = bv.x; Bs[lc + 1][lr] = bv.y;
        Bs[lc + 2][lr] = bv.z; Bs[lc + 3][lr] = bv.w;
        __syncthreads();
#pragma unroll
        for (int k = 0; k < 16; k++) {
            float4 a = *(const float4*)&As[k][ty << 2];
            float4 b = *(const float4*)&Bs[k][tx << 2];
            acc[0][0] += a.x * b.x; acc[0][1] += a.x * b.y; acc[0][2] += a.x * b.z; acc[0][3] += a.x * b.w;
            acc[1][0] += a.y * b.x; acc[1][1] += a.y * b.y; acc[1][2] += a.y * b.z; acc[1][3] += a.y * b.w;
            acc[2][0] += a.z * b.x; acc[2][1] += a.z * b.y; acc[2][2] += a.z * b.z; acc[2][3] += a.z * b.w;
            acc[3][0] += a.w * b.x; acc[3][1] += a.w * b.y; acc[3][2] += a.w * b.z; acc[3][3] += a.w * b.w;
        }
        __syncthreads();
    }
#pragma unroll
    for (int i = 0; i < 4; i++) {
        int row = m0 + (ty << 2) + i;
#pragma unroll
        for (int j = 0; j < 4; j++) {
            int col = n0 + (tx << 2) + j;
            float v = acc[i][j];
            if (bias) v += bias[col];
            if (res)  v += res[(size_t)row * N + col];
            C[(size_t)row * N + col] = v;
        }
    }
}

// ---------------- attention: scores S = scale * Q K^T (causal mask) -----------
__global__ void k_scores() {
    int kt = blockIdx.x, qt = blockIdx.y, bh = blockIdx.z;
    int b = bh / Hn, h = bh % Hn;
    int tid = threadIdx.x;
    int q0 = qt << 5, k0 = kt << 5;
    size_t outbase = (size_t)bh * Tn * Tn;
    int qi = tid >> 3;                 // 0..31
    int kk = (tid & 7) << 2;           // 0..28
    if (kt > qt) {                     // fully masked tile: write -1e30
#pragma unroll
        for (int j = 0; j < 4; j++)
            g_att[outbase + (size_t)(q0 + qi) * Tn + k0 + kk + j] = -1e30f;
        return;
    }
    __shared__ float Qs[32][65];
    __shared__ float Ks[32][65];
    const float* qsrc = g_qkv + (size_t)b * Tn * E3 + h * HDn;
    const float* ksrc = qsrc + En;
#pragma unroll
    for (int i = 0; i < 8; i++) {
        int lin = tid + (i << 8);
        int r = lin >> 6, d = lin & 63;
        Qs[r][d] = qsrc[(size_t)(q0 + r) * E3 + d];
        Ks[r][d] = ksrc[(size_t)(k0 + r) * E3 + d];
    }
    __syncthreads();
    float acc[4] = {};
#pragma unroll
    for (int d = 0; d < 64; d++) {
        float qv = Qs[qi][d];
        acc[0] += qv * Ks[kk + 0][d];
        acc[1] += qv * Ks[kk + 1][d];
        acc[2] += qv * Ks[kk + 2][d];
        acc[3] += qv * Ks[kk + 3][d];
    }
#pragma unroll
    for (int j = 0; j < 4; j++) {
        int kg = k0 + kk + j;
        float v = (kg <= q0 + qi) ? acc[j] * 0.125f : -1e30f;
        g_att[outbase + (size_t)(q0 + qi) * Tn + kg] = v;
    }
}

// ---------------- attention: row softmax ---------------------------------------
__global__ void k_softmax() {
    int row = blockIdx.x;                       // 0..49151
    float* p = g_att + (size_t)row * Tn;
    int tid = threadIdx.x;
    float v[4];
    float m = -1e30f;
#pragma unroll
    for (int i = 0; i < 4; i++) { v[i] = p[tid + (i << 8)]; m = fmaxf(m, v[i]); }
    __shared__ float sh[256];
    sh[tid] = m; __syncthreads();
    for (int st = 128; st > 0; st >>= 1) {
        if (tid < st) sh[tid] = fmaxf(sh[tid], sh[tid + st]);
        __syncthreads();
    }
    m = sh[0];
    __syncthreads();
    float s = 0.f;
#pragma unroll
    for (int i = 0; i < 4; i++) { v[i] = __expf(v[i] - m); s += v[i]; }
    sh[tid] = s; __syncthreads();
    for (int st = 128; st > 0; st >>= 1) {
        if (tid < st) sh[tid] += sh[tid + st];
        __syncthreads();
    }
    float inv = 1.f / sh[0];
#pragma unroll
    for (int i = 0; i < 4; i++) p[tid + (i << 8)] = v[i] * inv;
}

// ---------------- attention: Y = P @ V -----------------------------------------
__global__ void k_av() {
    int qt = blockIdx.x;               // 0..31
    int bh = blockIdx.y;               // 0..47
    int b = bh / Hn, h = bh % Hn;
    __shared__ float Ps[32][33];
    __shared__ __align__(16) float Vs[32][64];
    int tid = threadIdx.x;
    int q = tid >> 3;                  // 0..31
    int d0 = (tid & 7) << 3;           // 0..56
    float acc[8] = {};
    int q0 = qt << 5;
    size_t attbase = (size_t)bh * Tn * Tn + (size_t)q0 * Tn;
    const float* vsrc = g_qkv + (size_t)b * Tn * E3 + 2 * En + h * HDn;
    for (int kt = 0; kt <= qt; kt++) {
#pragma unroll
        for (int i = 0; i < 4; i++) {
            int lin = tid + (i << 8);
            int r = lin >> 5, c = lin & 31;
            Ps[r][c] = g_att[attbase + (size_t)r * Tn + (kt << 5) + c];
        }
#pragma unroll
        for (int i = 0; i < 8; i++) {
            int lin = tid + (i << 8);
            int r = lin >> 6, d = lin & 63;
            Vs[r][d] = vsrc[(size_t)((kt << 5) + r) * E3 + d];
        }
        __syncthreads();
#pragma unroll
        for (int k = 0; k < 32; k++) {
            float pv = Ps[q][k];
            float4 v0 = *(const float4*)&Vs[k][d0];
            float4 v1 = *(const float4*)&Vs[k][d0 + 4];
            acc[0] += pv * v0.x; acc[1] += pv * v0.y; acc[2] += pv * v0.z; acc[3] += pv * v0.w;
            acc[4] += pv * v1.x; acc[5] += pv * v1.y; acc[6] += pv * v1.z; acc[7] += pv * v1.w;
        }
        __syncthreads();
    }
    float* ydst = g_y + (size_t)(b * Tn + q0 + q) * En + h * HDn + d0;
#pragma unroll
    for (int j = 0; j < 8; j++) ydst[j] = acc[j];
}

// ---------------- GELU (tanh approx) -------------------------------------------
__global__ void k_gelu(float* __restrict__ p, int n) {
    int i = blockIdx.x * blockDim.x + threadIdx.x;
    if (i < n) {
        float x = p[i];
        float t = tanhf(0.7978845608028654f * (x + 0.044715f * x * x * x));
        p[i] = 0.5f * x * (1.f + t);
    }
}

// ---------------- loss: per-row logsumexp - target logit -----------------------
__global__ void k_lossrow(const float* __restrict__ logits, const int* __restrict__ targets) {
    int row = blockIdx.x;
    int tid = threadIdx.x;
    const float* p = logits + (size_t)row * Vn;
    float m = -1e30f;
    for (int j = tid; j < Vn; j += 256) m = fmaxf(m, p[j]);
    __shared__ float sh[256];
    sh[tid] = m; __syncthreads();
    for (int st = 128; st > 0; st >>= 1) {
        if (tid < st) sh[tid] = fmaxf(sh[tid], sh[tid + st]);
        __syncthreads();
    }
    m = sh[0];
    __syncthreads();
    float s = 0.f;
    for (int j = tid; j < Vn; j += 256) s += expf(p[j] - m);
    sh[tid] = s; __syncthreads();
    for (int st = 128; st > 0; st >>= 1) {
        if (tid < st) sh[tid] += sh[tid + st];
        __syncthreads();
    }
    if (tid == 0) {
        float lse = m + logf(sh[0]);
        g_rowloss[row] = lse - p[targets[row]];
    }
}

__global__ void k_lossreduce(float* __restrict__ out) {
    int tid = threadIdx.x;
    float s = 0.f;
    for (int i = tid; i < Mrows; i += 256) s += g_rowloss[i];
    __shared__ float sh[256];
    sh[tid] = s; __syncthreads();
    for (int st = 128; st > 0; st >>= 1) {
        if (tid < st) sh[tid] += sh[tid + st];
        __syncthreads();
    }
    if (tid == 0) out[0] = sh[0] * (1.f / Mrows);
}

// ---------------- launch --------------------------------------------------------
extern "C" void kernel_launch(void* const* d_in, const int* in_sizes, int n_in,
                              void* d_out, int out_size) {
    const int*   idx     = (const int*)  d_in[0];
    const int*   targets = (const int*)  d_in[1];
    const float* wte     = (const float*)d_in[2];
    const float* wpe     = (const float*)d_in[3];
    const float* ln1_g   = (const float*)d_in[4];
    const float* ln1_b   = (const float*)d_in[5];
    const float* attn_w  = (const float*)d_in[6];
    const float* attn_b  = (const float*)d_in[7];
    const float* proj_w  = (const float*)d_in[8];
    const float* proj_b  = (const float*)d_in[9];
    const float* ln2_g   = (const float*)d_in[10];
    const float* ln2_b   = (const float*)d_in[11];
    const float* fc_w    = (const float*)d_in[12];
    const float* fc_b    = (const float*)d_in[13];
    const float* fc2_w   = (const float*)d_in[14];
    const float* fc2_b   = (const float*)d_in[15];
    const float* lnf_g   = (const float*)d_in[16];
    const float* lnf_b   = (const float*)d_in[17];
    const float* lm_w    = (const float*)d_in[18];
    float* logits = (float*)d_out;

    float *px, *ph, *pqkv, *py, *pfc;
    cudaGetSymbolAddress((void**)&px,   g_x);
    cudaGetSymbolAddress((void**)&ph,   g_h);
    cudaGetSymbolAddress((void**)&pqkv, g_qkv);
    cudaGetSymbolAddress((void**)&py,   g_y);
    cudaGetSymbolAddress((void**)&pfc,  g_fc);

    k_embed<<<Mrows, 256>>>(idx, wte, wpe);

    for (int l = 0; l < Ln; l++) {
        // attention
        k_ln<<<Mrows, 256>>>(px, ph, ln1_g + (size_t)l * En, ln1_b + (size_t)l * En);
        k_gemm<<<dim3(E3 / 64, Mrows / 64), 256>>>(
            ph, attn_w + (size_t)l * E3 * En, attn_b + (size_t)l * E3, nullptr,
            pqkv, Mrows, E3, En);
        k_scores<<<dim3(Tn / 32, Tn / 32, Bn * Hn), 256>>>();
        k_softmax<<<Bn * Hn * Tn, 256>>>();
        k_av<<<dim3(Tn / 32, Bn * Hn), 256>>>();
        k_gemm<<<dim3(En / 64, Mrows / 64), 256>>>(
            py, proj_w + (size_t)l * En * En, proj_b + (size_t)l * En, px,
            px, Mrows, En, En);
        // mlp
        k_ln<<<Mrows, 256>>>(px, ph, ln2_g + (size_t)l * En, ln2_b + (size_t)l * En);
        k_gemm<<<dim3(E4 / 64, Mrows / 64), 256>>>(
            ph, fc_w + (size_t)l * E4 * En, fc_b + (size_t)l * E4, nullptr,
            pfc, Mrows, E4, En);
        k_gelu<<<(Mrows * E4) / 256, 256>>>(pfc, Mrows * E4);
        k_gemm<<<dim3(En / 64, Mrows / 64), 256>>>(
            pfc, fc2_w + (size_t)l * En * E4, fc2_b + (size_t)l * En, px,
            px, Mrows, En, E4);
    }

    // final ln + lm head + loss
    k_ln<<<Mrows, 256>>>(px, ph, lnf_g, lnf_b);
    k_gemm<<<dim3(Vn / 64, Mrows / 64), 256>>>(
        ph, lm_w, nullptr, nullptr, logits, Mrows, Vn, En);
    k_lossrow<<<Mrows, 256>>>(logits, targets);
    k_lossreduce<<<1, 256>>>(logits + (size_t)Mrows * Vn);
}

// round 4
// speedup vs baseline: 2.1100x; 2.1100x over previous
#include <cuda_runtime.h>
#include <cuda_bf16.h>
#include <math.h>
#include <cstdint>

// GPT-2 small forward: B=4, T=1024, E=768, H=12, HD=64, V=50304, L=12
#define Bn   4
#define Tn   1024
#define En   768
#define Hn   12
#define HDn  64
#define Vn   50304
#define Ln   12
#define Mrows 4096           // B*T
#define E3   2304
#define E4   3072

// ---------------- scratch (device globals; no allocation allowed) -------------
__device__ float g_x[Mrows * En];
__device__ float g_h[Mrows * En];
__device__ float g_qkv[Mrows * E3];
__device__ float g_y[Mrows * En];
__device__ float g_fc[Mrows * E4];
__device__ float g_att[(size_t)Bn * Hn * Tn * Tn];
__device__ float g_rowloss[Mrows];

// =============================== PTX helpers ==================================
__device__ __forceinline__ uint32_t smem_u32(const void* p) {
    uint32_t a;
    asm("{ .reg .u64 t; cvta.to.shared.u64 t, %1; cvt.u32.u64 %0, t; }"
        : "=r"(a) : "l"(p));
    return a;
}

__device__ __forceinline__ void ldsm4(uint32_t* r, uint32_t addr) {
    asm volatile("ldmatrix.sync.aligned.m8n8.x4.shared.b16 {%0,%1,%2,%3}, [%4];"
                 : "=r"(r[0]), "=r"(r[1]), "=r"(r[2]), "=r"(r[3]) : "r"(addr));
}

__device__ __forceinline__ void mma16816(float* d, const uint32_t* a,
                                         uint32_t b0, uint32_t b1) {
    asm volatile(
        "mma.sync.aligned.m16n8k16.row.col.f32.bf16.bf16.f32 "
        "{%0,%1,%2,%3}, {%4,%5,%6,%7}, {%8,%9}, {%0,%1,%2,%3};"
        : "+f"(d[0]), "+f"(d[1]), "+f"(d[2]), "+f"(d[3])
        : "r"(a[0]), "r"(a[1]), "r"(a[2]), "r"(a[3]), "r"(b0), "r"(b1));
}

// split a float4 into bf16 hi + bf16 lo, store as 8B each
__device__ __forceinline__ void split_store(float4 v, __nv_bfloat16* hi, __nv_bfloat16* lo) {
    __nv_bfloat162 h0 = __float22bfloat162_rn(make_float2(v.x, v.y));
    __nv_bfloat162 h1 = __float22bfloat162_rn(make_float2(v.z, v.w));
    float2 f0 = __bfloat1622float2(h0);
    float2 f1 = __bfloat1622float2(h1);
    __nv_bfloat162 l0 = __float22bfloat162_rn(make_float2(v.x - f0.x, v.y - f0.y));
    __nv_bfloat162 l1 = __float22bfloat162_rn(make_float2(v.z - f1.x, v.w - f1.y));
    uint2 uh, ul;
    uh.x = *(uint32_t*)&h0; uh.y = *(uint32_t*)&h1;
    ul.x = *(uint32_t*)&l0; ul.y = *(uint32_t*)&l1;
    *(uint2*)hi = uh;
    *(uint2*)lo = ul;
}

// ======================= bf16x3 mma.sync GEMM =================================
// C[M,N] = A[M,K] @ W[N,K]^T (+bias, +res). CTA tile 128x128, BK=32.
// smem per stage (halves): As_hi[128*40] As_lo Ws_hi Ws_lo = 20480 halves.
#define PSTR 40                     // padded row stride in halves
#define STAGE_H (4 * 128 * PSTR)    // 20480 halves per stage
#define GEMM_SMEM (2 * STAGE_H * 2) // 81920 bytes

__global__ void __launch_bounds__(256, 1)
k_gemm_mma(const float* __restrict__ A, const float* __restrict__ W,
           const float* __restrict__ bias, const float* __restrict__ res,
           float* __restrict__ C, int M, int N, int K) {
    extern __shared__ __align__(16) __nv_bfloat16 sm[];
    const int tid = threadIdx.x, lane = tid & 31, wid = tid >> 5;
    const int m0 = blockIdx.x << 7, n0 = blockIdx.y << 7;
    const int wm = (wid & 3) << 5;    // warp M offset
    const int wn = (wid >> 2) << 6;   // warp N offset

    // gmem tile loading: thread handles rows lr, lr+32, lr+64, lr+96 at cols lc..lc+3
    const int lr = tid >> 3;          // 0..31
    const int lc = (tid & 7) << 2;    // 0..28
    const float* Ap = A + (size_t)(m0 + lr) * K + lc;
    const float* Wp = W + (size_t)(n0 + lr) * K + lc;

    float4 ra[4], rw[4];
    float acc[2][8][4];
#pragma unroll
    for (int i = 0; i < 2; i++)
#pragma unroll
        for (int j = 0; j < 8; j++)
#pragma unroll
            for (int q = 0; q < 4; q++) acc[i][j][q] = 0.f;

    const int nk = K >> 5;

    // ldmatrix source addresses (byte offsets within a stage)
    const int arow = wm + (lane & 15);
    const int akk  = (lane >> 4) << 3;
    const uint32_t a_off = (uint32_t)(arow * PSTR + akk) << 1;
    // B (non-trans): lanes 0-7 -> n rows 0-7 @k0; 8-15 -> n 0-7 @k8;
    //                16-23 -> n 8-15 @k0; 24-31 -> n 8-15 @k8
    const int brow = wn + (lane & 7) + ((lane >> 4) << 3);
    const int bkk  = ((lane >> 3) & 1) << 3;
    const uint32_t b_off = (uint32_t)(10240 << 1) + ((uint32_t)(brow * PSTR + bkk) << 1);
    const uint32_t smb = smem_u32(sm);

#define LOADREGS(c)                                                           \
    {                                                                         \
        const size_t kb = (size_t)(c) << 5;                                   \
        _Pragma("unroll")                                                     \
        for (int i = 0; i < 4; i++) {                                         \
            ra[i] = *(const float4*)(Ap + (size_t)(i << 5) * K + kb);         \
            rw[i] = *(const float4*)(Wp + (size_t)(i << 5) * K + kb);         \
        }                                                                     \
    }

#define STOREREGS(s)                                                          \
    {                                                                         \
        __nv_bfloat16* base = sm + (s) * STAGE_H;                             \
        _Pragma("unroll")                                                     \
        for (int i = 0; i < 4; i++) {                                         \
            int off = (lr + (i << 5)) * PSTR + lc;                            \
            split_store(ra[i], base + off, base + 5120 + off);                \
            split_store(rw[i], base + 10240 + off, base + 15360 + off);       \
        }                                                                     \
    }

    LOADREGS(0);
    STOREREGS(0);
    __syncthreads();

    for (int c = 0; c < nk; c++) {
        const int s = c & 1;
        if (c + 1 < nk) LOADREGS(c + 1);

        const uint32_t stb = smb + (uint32_t)s * (STAGE_H * 2);
#pragma unroll
        for (int kc = 0; kc < 2; kc++) {
            uint32_t ah[2][4], al[2][4];
#pragma unroll
            for (int mi = 0; mi < 2; mi++) {
                uint32_t ad = stb + a_off + mi * 1280 + kc * 32;
                ldsm4(ah[mi], ad);
                ldsm4(al[mi], ad + 10240);
            }
#pragma unroll
            for (int j4 = 0; j4 < 4; j4++) {
                uint32_t bd = stb + b_off + j4 * 1280 + kc * 32;
                uint32_t bh[4], bl[4];
                ldsm4(bh, bd);
                ldsm4(bl, bd + 10240);
#pragma unroll
                for (int mi = 0; mi < 2; mi++) {
#pragma unroll
                    for (int nt = 0; nt < 2; nt++) {
                        float* d = acc[mi][j4 * 2 + nt];
                        mma16816(d, ah[mi], bh[2 * nt], bh[2 * nt + 1]);
                        mma16816(d, ah[mi], bl[2 * nt], bl[2 * nt + 1]);
                        mma16816(d, al[mi], bh[2 * nt], bh[2 * nt + 1]);
                    }
                }
            }
        }
        if (c + 1 < nk) STOREREGS((c + 1) & 1);
        __syncthreads();
    }

    // epilogue: accum regs -> gmem with bias/residual
#pragma unroll
    for (int mi = 0; mi < 2; mi++) {
#pragma unroll
        for (int j = 0; j < 8; j++) {
            const int row = m0 + wm + mi * 16 + (lane >> 2);
            const int col = n0 + wn + j * 8 + ((lane & 3) << 1);
            float bx = 0.f, by = 0.f;
            if (bias) { float2 b2 = *(const float2*)(bias + col); bx = b2.x; by = b2.y; }
#pragma unroll
            for (int hh = 0; hh < 2; hh++) {
                float vx = acc[mi][j][hh * 2 + 0] + bx;
                float vy = acc[mi][j][hh * 2 + 1] + by;
                const size_t go = (size_t)(row + hh * 8) * N + col;
                if (res) { float2 r2 = *(const float2*)(res + go); vx += r2.x; vy += r2.y; }
                float2 o2; o2.x = vx; o2.y = vy;
                *(float2*)(C + go) = o2;
            }
        }
    }
#undef LOADREGS
#undef STOREREGS
}

// ---------------- embedding ---------------------------------------------------
__global__ void k_embed(const int* __restrict__ idx,
                        const float* __restrict__ wte,
                        const float* __restrict__ wpe) {
    int row = blockIdx.x;
    int t = row & (Tn - 1);
    int tok = idx[row];
    const float* src = wte + (size_t)tok * En;
    const float* pos = wpe + (size_t)t * En;
    float* dst = g_x + (size_t)row * En;
    for (int e = threadIdx.x; e < En; e += blockDim.x)
        dst[e] = src[e] + pos[e];
}

// ---------------- layernorm ----------------------------------------------------
__global__ void k_ln(const float* __restrict__ in, float* __restrict__ out,
                     const float* __restrict__ g, const float* __restrict__ b) {
    int row = blockIdx.x;
    int tid = threadIdx.x;
    const float* x = in + (size_t)row * En;
    float s = 0.f, ss = 0.f;
    for (int e = tid; e < En; e += 256) { float v = x[e]; s += v; ss += v * v; }
    __shared__ float sh[512];
    sh[tid] = s; sh[256 + tid] = ss;
    __syncthreads();
    for (int st = 128; st > 0; st >>= 1) {
        if (tid < st) { sh[tid] += sh[tid + st]; sh[256 + tid] += sh[256 + tid + st]; }
        __syncthreads();
    }
    float mean = sh[0] * (1.f / En);
    float var  = sh[256] * (1.f / En) - mean * mean;
    float rstd = rsqrtf(var + 1e-5f);
    float* o = out + (size_t)row * En;
    for (int e = tid; e < En; e += 256)
        o[e] = (x[e] - mean) * rstd * g[e] + b[e];
}

// ---------------- attention: scores S = scale * Q K^T (causal mask) -----------
__global__ void k_scores() {
    int kt = blockIdx.x, qt = blockIdx.y, bh = blockIdx.z;
    int b = bh / Hn, h = bh % Hn;
    int tid = threadIdx.x;
    int q0 = qt << 5, k0 = kt << 5;
    size_t outbase = (size_t)bh * Tn * Tn;
    int qi = tid >> 3;
    int kk = (tid & 7) << 2;
    if (kt > qt) {
#pragma unroll
        for (int j = 0; j < 4; j++)
            g_att[outbase + (size_t)(q0 + qi) * Tn + k0 + kk + j] = -1e30f;
        return;
    }
    __shared__ float Qs[32][65];
    __shared__ float Ks[32][65];
    const float* qsrc = g_qkv + (size_t)b * Tn * E3 + h * HDn;
    const float* ksrc = qsrc + En;
#pragma unroll
    for (int i = 0; i < 8; i++) {
        int lin = tid + (i << 8);
        int r = lin >> 6, d = lin & 63;
        Qs[r][d] = qsrc[(size_t)(q0 + r) * E3 + d];
        Ks[r][d] = ksrc[(size_t)(k0 + r) * E3 + d];
    }
    __syncthreads();
    float acc[4] = {};
#pragma unroll
    for (int d = 0; d < 64; d++) {
        float qv = Qs[qi][d];
        acc[0] += qv * Ks[kk + 0][d];
        acc[1] += qv * Ks[kk + 1][d];
        acc[2] += qv * Ks[kk + 2][d];
        acc[3] += qv * Ks[kk + 3][d];
    }
#pragma unroll
    for (int j = 0; j < 4; j++) {
        int kg = k0 + kk + j;
        float v = (kg <= q0 + qi) ? acc[j] * 0.125f : -1e30f;
        g_att[outbase + (size_t)(q0 + qi) * Tn + kg] = v;
    }
}

// ---------------- attention: row softmax ---------------------------------------
__global__ void k_softmax() {
    int row = blockIdx.x;
    float* p = g_att + (size_t)row * Tn;
    int tid = threadIdx.x;
    float v[4];
    float m = -1e30f;
#pragma unroll
    for (int i = 0; i < 4; i++) { v[i] = p[tid + (i << 8)]; m = fmaxf(m, v[i]); }
    __shared__ float sh[256];
    sh[tid] = m; __syncthreads();
    for (int st = 128; st > 0; st >>= 1) {
        if (tid < st) sh[tid] = fmaxf(sh[tid], sh[tid + st]);
        __syncthreads();
    }
    m = sh[0];
    __syncthreads();
    float s = 0.f;
#pragma unroll
    for (int i = 0; i < 4; i++) { v[i] = __expf(v[i] - m); s += v[i]; }
    sh[tid] = s; __syncthreads();
    for (int st = 128; st > 0; st >>= 1) {
        if (tid < st) sh[tid] += sh[tid + st];
        __syncthreads();
    }
    float inv = 1.f / sh[0];
#pragma unroll
    for (int i = 0; i < 4; i++) p[tid + (i << 8)] = v[i] * inv;
}

// ---------------- attention: Y = P @ V -----------------------------------------
__global__ void k_av() {
    int qt = blockIdx.x;
    int bh = blockIdx.y;
    int b = bh / Hn, h = bh % Hn;
    __shared__ float Ps[32][33];
    __shared__ __align__(16) float Vs[32][64];
    int tid = threadIdx.x;
    int q = tid >> 3;
    int d0 = (tid & 7) << 3;
    float acc[8] = {};
    int q0 = qt << 5;
    size_t attbase = (size_t)bh * Tn * Tn + (size_t)q0 * Tn;
    const float* vsrc = g_qkv + (size_t)b * Tn * E3 + 2 * En + h * HDn;
    for (int kt = 0; kt <= qt; kt++) {
#pragma unroll
        for (int i = 0; i < 4; i++) {
            int lin = tid + (i << 8);
            int r = lin >> 5, c = lin & 31;
            Ps[r][c] = g_att[attbase + (size_t)r * Tn + (kt << 5) + c];
        }
#pragma unroll
        for (int i = 0; i < 8; i++) {
            int lin = tid + (i << 8);
            int r = lin >> 6, d = lin & 63;
            Vs[r][d] = vsrc[(size_t)((kt << 5) + r) * E3 + d];
        }
        __syncthreads();
#pragma unroll
        for (int k = 0; k < 32; k++) {
            float pv = Ps[q][k];
            float4 v0 = *(const float4*)&Vs[k][d0];
            float4 v1 = *(const float4*)&Vs[k][d0 + 4];
            acc[0] += pv * v0.x; acc[1] += pv * v0.y; acc[2] += pv * v0.z; acc[3] += pv * v0.w;
            acc[4] += pv * v1.x; acc[5] += pv * v1.y; acc[6] += pv * v1.z; acc[7] += pv * v1.w;
        }
        __syncthreads();
    }
    float* ydst = g_y + (size_t)(b * Tn + q0 + q) * En + h * HDn + d0;
#pragma unroll
    for (int j = 0; j < 8; j++) ydst[j] = acc[j];
}

// ---------------- GELU (tanh approx) -------------------------------------------
__global__ void k_gelu(float* __restrict__ p, int n) {
    int i = blockIdx.x * blockDim.x + threadIdx.x;
    if (i < n) {
        float x = p[i];
        float t = tanhf(0.7978845608028654f * (x + 0.044715f * x * x * x));
        p[i] = 0.5f * x * (1.f + t);
    }
}

// ---------------- loss ----------------------------------------------------------
__global__ void k_lossrow(const float* __restrict__ logits, const int* __restrict__ targets) {
    int row = blockIdx.x;
    int tid = threadIdx.x;
    const float* p = logits + (size_t)row * Vn;
    float m = -1e30f;
    for (int j = tid; j < Vn; j += 256) m = fmaxf(m, p[j]);
    __shared__ float sh[256];
    sh[tid] = m; __syncthreads();
    for (int st = 128; st > 0; st >>= 1) {
        if (tid < st) sh[tid] = fmaxf(sh[tid], sh[tid + st]);
        __syncthreads();
    }
    m = sh[0];
    __syncthreads();
    float s = 0.f;
    for (int j = tid; j < Vn; j += 256) s += expf(p[j] - m);
    sh[tid] = s; __syncthreads();
    for (int st = 128; st > 0; st >>= 1) {
        if (tid < st) sh[tid] += sh[tid + st];
        __syncthreads();
    }
    if (tid == 0) {
        float lse = m + logf(sh[0]);
        g_rowloss[row] = lse - p[targets[row]];
    }
}

__global__ void k_lossreduce(float* __restrict__ out) {
    int tid = threadIdx.x;
    float s = 0.f;
    for (int i = tid; i < Mrows; i += 256) s += g_rowloss[i];
    __shared__ float sh[256];
    sh[tid] = s; __syncthreads();
    for (int st = 128; st > 0; st >>= 1) {
        if (tid < st) sh[tid] += sh[tid + st];
        __syncthreads();
    }
    if (tid == 0) out[0] = sh[0] * (1.f / Mrows);
}

// ---------------- launch --------------------------------------------------------
extern "C" void kernel_launch(void* const* d_in, const int* in_sizes, int n_in,
                              void* d_out, int out_size) {
    const int*   idx     = (const int*)  d_in[0];
    const int*   targets = (const int*)  d_in[1];
    const float* wte     = (const float*)d_in[2];
    const float* wpe     = (const float*)d_in[3];
    const float* ln1_g   = (const float*)d_in[4];
    const float* ln1_b   = (const float*)d_in[5];
    const float* attn_w  = (const float*)d_in[6];
    const float* attn_b  = (const float*)d_in[7];
    const float* proj_w  = (const float*)d_in[8];
    const float* proj_b  = (const float*)d_in[9];
    const float* ln2_g   = (const float*)d_in[10];
    const float* ln2_b   = (const float*)d_in[11];
    const float* fc_w    = (const float*)d_in[12];
    const float* fc_b    = (const float*)d_in[13];
    const float* fc2_w   = (const float*)d_in[14];
    const float* fc2_b   = (const float*)d_in[15];
    const float* lnf_g   = (const float*)d_in[16];
    const float* lnf_b   = (const float*)d_in[17];
    const float* lm_w    = (const float*)d_in[18];
    float* logits = (float*)d_out;

    float *px, *ph, *pqkv, *py, *pfc;
    cudaGetSymbolAddress((void**)&px,   g_x);
    cudaGetSymbolAddress((void**)&ph,   g_h);
    cudaGetSymbolAddress((void**)&pqkv, g_qkv);
    cudaGetSymbolAddress((void**)&py,   g_y);
    cudaGetSymbolAddress((void**)&pfc,  g_fc);

    cudaFuncSetAttribute(k_gemm_mma, cudaFuncAttributeMaxDynamicSharedMemorySize, GEMM_SMEM);

    k_embed<<<Mrows, 256>>>(idx, wte, wpe);

    for (int l = 0; l < Ln; l++) {
        // attention
        k_ln<<<Mrows, 256>>>(px, ph, ln1_g + (size_t)l * En, ln1_b + (size_t)l * En);
        k_gemm_mma<<<dim3(Mrows / 128, E3 / 128), 256, GEMM_SMEM>>>(
            ph, attn_w + (size_t)l * E3 * En, attn_b + (size_t)l * E3, nullptr,
            pqkv, Mrows, E3, En);
        k_scores<<<dim3(Tn / 32, Tn / 32, Bn * Hn), 256>>>();
        k_softmax<<<Bn * Hn * Tn, 256>>>();
        k_av<<<dim3(Tn / 32, Bn * Hn), 256>>>();
        k_gemm_mma<<<dim3(Mrows / 128, En / 128), 256, GEMM_SMEM>>>(
            py, proj_w + (size_t)l * En * En, proj_b + (size_t)l * En, px,
            px, Mrows, En, En);
        // mlp
        k_ln<<<Mrows, 256>>>(px, ph, ln2_g + (size_t)l * En, ln2_b + (size_t)l * En);
        k_gemm_mma<<<dim3(Mrows / 128, E4 / 128), 256, GEMM_SMEM>>>(
            ph, fc_w + (size_t)l * E4 * En, fc_b + (size_t)l * E4, nullptr,
            pfc, Mrows, E4, En);
        k_gelu<<<(Mrows * E4) / 256, 256>>>(pfc, Mrows * E4);
        k_gemm_mma<<<dim3(Mrows / 128, En / 128), 256, GEMM_SMEM>>>(
            pfc, fc2_w + (size_t)l * En * E4, fc2_b + (size_t)l * En, px,
            px, Mrows, En, E4);
    }

    // final ln + lm head + loss
    k_ln<<<Mrows, 256>>>(px, ph, lnf_g, lnf_b);
    k_gemm_mma<<<dim3(Mrows / 128, Vn / 128), 256, GEMM_SMEM>>>(
        ph, lm_w, nullptr, nullptr, logits, Mrows, Vn, En);
    k_lossrow<<<Mrows, 256>>>(logits, targets);
    k_lossreduce<<<1, 256>>>(logits + (size_t)Mrows * Vn);
}

// round 5
// speedup vs baseline: 3.7104x; 1.7585x over previous
#include <cuda_runtime.h>
#include <cuda_bf16.h>
#include <math.h>
#include <cstdint>

// GPT-2 small forward: B=4, T=1024, E=768, H=12, HD=64, V=50304, L=12
#define Bn   4
#define Tn   1024
#define En   768
#define Hn   12
#define HDn  64
#define Vn   50304
#define Ln   12
#define Mrows 4096           // B*T
#define E3   2304
#define E4   3072

// ---------------- scratch (device globals; no allocation allowed) -------------
__device__ float g_x[Mrows * En];
__device__ float g_h[Mrows * En];
__device__ float g_qkv[Mrows * E3];
__device__ float g_y[Mrows * En];
__device__ float g_fc[Mrows * E4];
__device__ float g_rowloss[Mrows];

// =============================== PTX helpers ==================================
__device__ __forceinline__ uint32_t smem_u32(const void* p) {
    uint32_t a;
    asm("{ .reg .u64 t; cvta.to.shared.u64 t, %1; cvt.u32.u64 %0, t; }"
        : "=r"(a) : "l"(p));
    return a;
}

__device__ __forceinline__ void ldsm4(uint32_t* r, uint32_t addr) {
    asm volatile("ldmatrix.sync.aligned.m8n8.x4.shared.b16 {%0,%1,%2,%3}, [%4];"
                 : "=r"(r[0]), "=r"(r[1]), "=r"(r[2]), "=r"(r[3]) : "r"(addr));
}

__device__ __forceinline__ void ldsm4t(uint32_t* r, uint32_t addr) {
    asm volatile("ldmatrix.sync.aligned.m8n8.x4.trans.shared.b16 {%0,%1,%2,%3}, [%4];"
                 : "=r"(r[0]), "=r"(r[1]), "=r"(r[2]), "=r"(r[3]) : "r"(addr));
}

__device__ __forceinline__ void mma16816(float* d, const uint32_t* a,
                                         uint32_t b0, uint32_t b1) {
    asm volatile(
        "mma.sync.aligned.m16n8k16.row.col.f32.bf16.bf16.f32 "
        "{%0,%1,%2,%3}, {%4,%5,%6,%7}, {%8,%9}, {%0,%1,%2,%3};"
        : "+f"(d[0]), "+f"(d[1]), "+f"(d[2]), "+f"(d[3])
        : "r"(a[0]), "r"(a[1]), "r"(a[2]), "r"(a[3]), "r"(b0), "r"(b1));
}

// split a float4 into bf16 hi + bf16 lo, store as 8B each
__device__ __forceinline__ void split_store(float4 v, __nv_bfloat16* hi, __nv_bfloat16* lo) {
    __nv_bfloat162 h0 = __float22bfloat162_rn(make_float2(v.x, v.y));
    __nv_bfloat162 h1 = __float22bfloat162_rn(make_float2(v.z, v.w));
    float2 f0 = __bfloat1622float2(h0);
    float2 f1 = __bfloat1622float2(h1);
    __nv_bfloat162 l0 = __float22bfloat162_rn(make_float2(v.x - f0.x, v.y - f0.y));
    __nv_bfloat162 l1 = __float22bfloat162_rn(make_float2(v.z - f1.x, v.w - f1.y));
    uint2 uh, ul;
    uh.x = *(uint32_t*)&h0; uh.y = *(uint32_t*)&h1;
    ul.x = *(uint32_t*)&l0; ul.y = *(uint32_t*)&l1;
    *(uint2*)hi = uh;
    *(uint2*)lo = ul;
}

// pack 2 floats to bf16x2 hi, return lo residual pack
__device__ __forceinline__ uint32_t pack_split(float x, float y, uint32_t* lo) {
    __nv_bfloat162 h = __float22bfloat162_rn(make_float2(x, y));
    float2 f = __bfloat1622float2(h);
    __nv_bfloat162 l = __float22bfloat162_rn(make_float2(x - f.x, y - f.y));
    *lo = *(uint32_t*)&l;
    return *(uint32_t*)&h;
}

// ======================= bf16x3 mma.sync GEMM =================================
#define PSTR 40
#define STAGE_H (4 * 128 * PSTR)
#define GEMM_SMEM (2 * STAGE_H * 2)

__global__ void __launch_bounds__(256, 1)
k_gemm_mma(const float* __restrict__ A, const float* __restrict__ W,
           const float* __restrict__ bias, const float* __restrict__ res,
           float* __restrict__ C, int M, int N, int K, int act) {
    extern __shared__ __align__(16) __nv_bfloat16 sm[];
    const int tid = threadIdx.x, lane = tid & 31, wid = tid >> 5;
    const int m0 = blockIdx.x << 7, n0 = blockIdx.y << 7;
    const int wm = (wid & 3) << 5;
    const int wn = (wid >> 2) << 6;

    const int lr = tid >> 3;
    const int lc = (tid & 7) << 2;
    const float* Ap = A + (size_t)(m0 + lr) * K + lc;
    const float* Wp = W + (size_t)(n0 + lr) * K + lc;

    float4 ra[4], rw[4];
    float acc[2][8][4];
#pragma unroll
    for (int i = 0; i < 2; i++)
#pragma unroll
        for (int j = 0; j < 8; j++)
#pragma unroll
            for (int q = 0; q < 4; q++) acc[i][j][q] = 0.f;

    const int nk = K >> 5;

    const int arow = wm + (lane & 15);
    const int akk  = (lane >> 4) << 3;
    const uint32_t a_off = (uint32_t)(arow * PSTR + akk) << 1;
    const int brow = wn + (lane & 7) + ((lane >> 4) << 3);
    const int bkk  = ((lane >> 3) & 1) << 3;
    const uint32_t b_off = (uint32_t)(10240 << 1) + ((uint32_t)(brow * PSTR + bkk) << 1);
    const uint32_t smb = smem_u32(sm);

#define LOADREGS(c)                                                           \
    {                                                                         \
        const size_t kb = (size_t)(c) << 5;                                   \
        _Pragma("unroll")                                                     \
        for (int i = 0; i < 4; i++) {                                         \
            ra[i] = *(const float4*)(Ap + (size_t)(i << 5) * K + kb);         \
            rw[i] = *(const float4*)(Wp + (size_t)(i << 5) * K + kb);         \
        }                                                                     \
    }

#define STOREREGS(s)                                                          \
    {                                                                         \
        __nv_bfloat16* base = sm + (s) * STAGE_H;                             \
        _Pragma("unroll")                                                     \
        for (int i = 0; i < 4; i++) {                                         \
            int off = (lr + (i << 5)) * PSTR + lc;                            \
            split_store(ra[i], base + off, base + 5120 + off);                \
            split_store(rw[i], base + 10240 + off, base + 15360 + off);       \
        }                                                                     \
    }

    LOADREGS(0);
    STOREREGS(0);
    __syncthreads();

    for (int c = 0; c < nk; c++) {
        const int s = c & 1;
        if (c + 1 < nk) LOADREGS(c + 1);

        const uint32_t stb = smb + (uint32_t)s * (STAGE_H * 2);
#pragma unroll
        for (int kc = 0; kc < 2; kc++) {
            uint32_t ah[2][4], al[2][4];
#pragma unroll
            for (int mi = 0; mi < 2; mi++) {
                uint32_t ad = stb + a_off + mi * 1280 + kc * 32;
                ldsm4(ah[mi], ad);
                ldsm4(al[mi], ad + 10240);
            }
#pragma unroll
            for (int j4 = 0; j4 < 4; j4++) {
                uint32_t bd = stb + b_off + j4 * 1280 + kc * 32;
                uint32_t bh[4], bl[4];
                ldsm4(bh, bd);
                ldsm4(bl, bd + 10240);
#pragma unroll
                for (int mi = 0; mi < 2; mi++) {
#pragma unroll
                    for (int nt = 0; nt < 2; nt++) {
                        float* d = acc[mi][j4 * 2 + nt];
                        mma16816(d, ah[mi], bh[2 * nt], bh[2 * nt + 1]);
                        mma16816(d, ah[mi], bl[2 * nt], bl[2 * nt + 1]);
                        mma16816(d, al[mi], bh[2 * nt], bh[2 * nt + 1]);
                    }
                }
            }
        }
        if (c + 1 < nk) STOREREGS((c + 1) & 1);
        __syncthreads();
    }

#pragma unroll
    for (int mi = 0; mi < 2; mi++) {
#pragma unroll
        for (int j = 0; j < 8; j++) {
            const int row = m0 + wm + mi * 16 + (lane >> 2);
            const int col = n0 + wn + j * 8 + ((lane & 3) << 1);
            float bx = 0.f, by = 0.f;
            if (bias) { float2 b2 = *(const float2*)(bias + col); bx = b2.x; by = b2.y; }
#pragma unroll
            for (int hh = 0; hh < 2; hh++) {
                float vx = acc[mi][j][hh * 2 + 0] + bx;
                float vy = acc[mi][j][hh * 2 + 1] + by;
                if (act) {
                    float t = tanhf(0.7978845608028654f * (vx + 0.044715f * vx * vx * vx));
                    vx = 0.5f * vx * (1.f + t);
                    t = tanhf(0.7978845608028654f * (vy + 0.044715f * vy * vy * vy));
                    vy = 0.5f * vy * (1.f + t);
                }
                const size_t go = (size_t)(row + hh * 8) * N + col;
                if (res) { float2 r2 = *(const float2*)(res + go); vx += r2.x; vy += r2.y; }
                float2 o2; o2.x = vx; o2.y = vy;
                *(float2*)(C + go) = o2;
            }
        }
    }
#undef LOADREGS
#undef STOREREGS
}

// ======================= fused flash attention ================================
// One CTA: 64 q-rows of one (b,h). 128 threads = 4 warps, 16 q-rows each.
// bf16x3 mma for QK^T and PV, fp32 online softmax.
// smem (halves): Qh 0, Ql 4608, Kh 9216, Kl 13824, Vh 18432, Vl 23040
#define FAP 72                       // padded row stride (halves)
#define FA_SEC (64 * FAP)            // 4608 halves per section
#define FA_SMEM (6 * FA_SEC * 2)     // 55296 bytes

__global__ void __launch_bounds__(128, 1) k_flash() {
    extern __shared__ __align__(16) __nv_bfloat16 fs[];
    const int tid = threadIdx.x, lane = tid & 31, w = tid >> 5;
    const int qt = blockIdx.x, bh = blockIdx.y;
    const int b = bh / Hn, h = bh % Hn;
    const float* base = g_qkv + (size_t)b * Tn * E3 + h * HDn;
    const uint32_t smb = smem_u32(fs);

    // load Q tile -> smem hi/lo
    {
        const int r = tid >> 1, c0 = (tid & 1) * 32;
        const float* src = base + (size_t)(qt * 64 + r) * E3 + c0;
#pragma unroll
        for (int i = 0; i < 8; i++) {
            float4 v = *(const float4*)(src + i * 4);
            split_store(v, fs + r * FAP + c0 + i * 4, fs + FA_SEC + r * FAP + c0 + i * 4);
        }
    }
    __syncthreads();

    // Q fragments: m16 x k64 (4 k-steps)
    uint32_t qh[4][4], ql[4][4];
    {
        const int ar = (w << 4) + (lane & 15);
        const int ak = (lane >> 4) << 3;
#pragma unroll
        for (int ks = 0; ks < 4; ks++) {
            uint32_t ad = smb + ((uint32_t)(ar * FAP + ks * 16 + ak) << 1);
            ldsm4(qh[ks], ad);
            ldsm4(ql[ks], ad + (FA_SEC << 1));
        }
    }

    float O[8][4];
#pragma unroll
    for (int j = 0; j < 8; j++)
#pragma unroll
        for (int q = 0; q < 4; q++) O[j][q] = 0.f;
    float m0 = -1e30f, m1 = -1e30f, l0 = 0.f, l1 = 0.f;

    // ldsm lane addressing (B operands)
    const int kbr = (lane & 7) + ((lane >> 4) << 3);   // K: n rows (non-trans)
    const int kbk = ((lane >> 3) & 1) << 3;
    const int vbr = (lane & 7) + (((lane >> 3) & 1) << 3); // V: k rows (trans)
    const int vbc = (lane >> 4) << 3;

    const int nkt = qt + 1;
    for (int kt = 0; kt < nkt; kt++) {
        __syncthreads();
        // load K, V tiles
        {
            const int r = tid >> 1, c0 = (tid & 1) * 32;
            const float* ksrc = base + En + (size_t)(kt * 64 + r) * E3 + c0;
            const float* vsrc = base + 2 * En + (size_t)(kt * 64 + r) * E3 + c0;
#pragma unroll
            for (int i = 0; i < 8; i++) {
                float4 kv = *(const float4*)(ksrc + i * 4);
                split_store(kv, fs + 2 * FA_SEC + r * FAP + c0 + i * 4,
                                fs + 3 * FA_SEC + r * FAP + c0 + i * 4);
                float4 vv = *(const float4*)(vsrc + i * 4);
                split_store(vv, fs + 4 * FA_SEC + r * FAP + c0 + i * 4,
                                fs + 5 * FA_SEC + r * FAP + c0 + i * 4);
            }
        }
        __syncthreads();

        // S = Q K^T  (m16 x n64, contraction over d=64)
        float S[8][4];
#pragma unroll
        for (int j = 0; j < 8; j++)
#pragma unroll
            for (int q = 0; q < 4; q++) S[j][q] = 0.f;
#pragma unroll
        for (int ks = 0; ks < 4; ks++) {
#pragma unroll
            for (int jp = 0; jp < 4; jp++) {
                uint32_t bd = smb + (uint32_t)(2 * FA_SEC << 1) +
                              ((uint32_t)((jp * 16 + kbr) * FAP + ks * 16 + kbk) << 1);
                uint32_t bhf[4], blf[4];
                ldsm4(bhf, bd);
                ldsm4(blf, bd + (FA_SEC << 1));
#pragma unroll
                for (int nt = 0; nt < 2; nt++) {
                    float* d = S[jp * 2 + nt];
                    mma16816(d, qh[ks], bhf[2 * nt], bhf[2 * nt + 1]);
                    mma16816(d, qh[ks], blf[2 * nt], blf[2 * nt + 1]);
                    mma16816(d, ql[ks], bhf[2 * nt], bhf[2 * nt + 1]);
                }
            }
        }
        // scale + causal mask (diagonal tile only)
#pragma unroll
        for (int j = 0; j < 8; j++)
#pragma unroll
            for (int q = 0; q < 4; q++) S[j][q] *= 0.125f;
        if (kt == qt) {
            const int rowg = (w << 4) + (lane >> 2);
            const int colb = (lane & 3) << 1;
#pragma unroll
            for (int j = 0; j < 8; j++) {
                const int cg = (j << 3) + colb;
                if (cg     > rowg)     S[j][0] = -1e30f;
                if (cg + 1 > rowg)     S[j][1] = -1e30f;
                if (cg     > rowg + 8) S[j][2] = -1e30f;
                if (cg + 1 > rowg + 8) S[j][3] = -1e30f;
            }
        }
        // online softmax (rows r = lane>>2 and r+8)
        float mx0 = -1e30f, mx1 = -1e30f;
#pragma unroll
        for (int j = 0; j < 8; j++) {
            mx0 = fmaxf(mx0, fmaxf(S[j][0], S[j][1]));
            mx1 = fmaxf(mx1, fmaxf(S[j][2], S[j][3]));
        }
        mx0 = fmaxf(mx0, __shfl_xor_sync(0xffffffffu, mx0, 1));
        mx0 = fmaxf(mx0, __shfl_xor_sync(0xffffffffu, mx0, 2));
        mx1 = fmaxf(mx1, __shfl_xor_sync(0xffffffffu, mx1, 1));
        mx1 = fmaxf(mx1, __shfl_xor_sync(0xffffffffu, mx1, 2));
        const float mn0 = fmaxf(m0, mx0), mn1 = fmaxf(m1, mx1);
        const float al0 = __expf(m0 - mn0), al1 = __expf(m1 - mn1);
        float rs0 = 0.f, rs1 = 0.f;
#pragma unroll
        for (int j = 0; j < 8; j++) {
            S[j][0] = __expf(S[j][0] - mn0);
            S[j][1] = __expf(S[j][1] - mn0);
            S[j][2] = __expf(S[j][2] - mn1);
            S[j][3] = __expf(S[j][3] - mn1);
            rs0 += S[j][0] + S[j][1];
            rs1 += S[j][2] + S[j][3];
        }
        rs0 += __shfl_xor_sync(0xffffffffu, rs0, 1);
        rs0 += __shfl_xor_sync(0xffffffffu, rs0, 2);
        rs1 += __shfl_xor_sync(0xffffffffu, rs1, 1);
        rs1 += __shfl_xor_sync(0xffffffffu, rs1, 2);
        l0 = l0 * al0 + rs0;
        l1 = l1 * al1 + rs1;
        m0 = mn0; m1 = mn1;
#pragma unroll
        for (int j = 0; j < 8; j++) {
            O[j][0] *= al0; O[j][1] *= al0;
            O[j][2] *= al1; O[j][3] *= al1;
        }
        // O += P @ V  (contraction over seq=64)
#pragma unroll
        for (int ks = 0; ks < 4; ks++) {
            uint32_t ph[4], pl[4];
            ph[0] = pack_split(S[2 * ks][0],     S[2 * ks][1],     &pl[0]);
            ph[1] = pack_split(S[2 * ks][2],     S[2 * ks][3],     &pl[1]);
            ph[2] = pack_split(S[2 * ks + 1][0], S[2 * ks + 1][1], &pl[2]);
            ph[3] = pack_split(S[2 * ks + 1][2], S[2 * ks + 1][3], &pl[3]);
#pragma unroll
            for (int jp = 0; jp < 4; jp++) {
                uint32_t vd = smb + (uint32_t)(4 * FA_SEC << 1) +
                              ((uint32_t)((ks * 16 + vbr) * FAP + jp * 16 + vbc) << 1);
                uint32_t vh[4], vl[4];
                ldsm4t(vh, vd);
                ldsm4t(vl, vd + (FA_SEC << 1));
#pragma unroll
                for (int nt = 0; nt < 2; nt++) {
                    float* d = O[jp * 2 + nt];
                    mma16816(d, ph, vh[2 * nt], vh[2 * nt + 1]);
                    mma16816(d, ph, vl[2 * nt], vl[2 * nt + 1]);
                    mma16816(d, pl, vh[2 * nt], vh[2 * nt + 1]);
                }
            }
        }
    }

    // write O / l to g_y
    const float il0 = 1.f / l0, il1 = 1.f / l1;
    const int row0 = qt * 64 + (w << 4) + (lane >> 2);
    float* yb = g_y + (size_t)(b * Tn + row0) * En + h * HDn + ((lane & 3) << 1);
#pragma unroll
    for (int j = 0; j < 8; j++) {
        float2 o0; o0.x = O[j][0] * il0; o0.y = O[j][1] * il0;
        float2 o1; o1.x = O[j][2] * il1; o1.y = O[j][3] * il1;
        *(float2*)(yb + j * 8) = o0;
        *(float2*)(yb + (size_t)8 * En + j * 8) = o1;
    }
}

// ---------------- embedding ---------------------------------------------------
__global__ void k_embed(const int* __restrict__ idx,
                        const float* __restrict__ wte,
                        const float* __restrict__ wpe) {
    int row = blockIdx.x;
    int t = row & (Tn - 1);
    int tok = idx[row];
    const float* src = wte + (size_t)tok * En;
    const float* pos = wpe + (size_t)t * En;
    float* dst = g_x + (size_t)row * En;
    for (int e = threadIdx.x; e < En; e += blockDim.x)
        dst[e] = src[e] + pos[e];
}

// ---------------- layernorm ----------------------------------------------------
__global__ void k_ln(const float* __restrict__ in, float* __restrict__ out,
                     const float* __restrict__ g, const float* __restrict__ b) {
    int row = blockIdx.x;
    int tid = threadIdx.x;
    const float* x = in + (size_t)row * En;
    float s = 0.f, ss = 0.f;
    for (int e = tid; e < En; e += 256) { float v = x[e]; s += v; ss += v * v; }
    __shared__ float sh[512];
    sh[tid] = s; sh[256 + tid] = ss;
    __syncthreads();
    for (int st = 128; st > 0; st >>= 1) {
        if (tid < st) { sh[tid] += sh[tid + st]; sh[256 + tid] += sh[256 + tid + st]; }
        __syncthreads();
    }
    float mean = sh[0] * (1.f / En);
    float var  = sh[256] * (1.f / En) - mean * mean;
    float rstd = rsqrtf(var + 1e-5f);
    float* o = out + (size_t)row * En;
    for (int e = tid; e < En; e += 256)
        o[e] = (x[e] - mean) * rstd * g[e] + b[e];
}

// ---------------- loss ----------------------------------------------------------
__global__ void k_lossrow(const float* __restrict__ logits, const int* __restrict__ targets) {
    int row = blockIdx.x;
    int tid = threadIdx.x;
    const float* p = logits + (size_t)row * Vn;
    float m = -1e30f;
    for (int j = tid; j < Vn; j += 256) m = fmaxf(m, p[j]);
    __shared__ float sh[256];
    sh[tid] = m; __syncthreads();
    for (int st = 128; st > 0; st >>= 1) {
        if (tid < st) sh[tid] = fmaxf(sh[tid], sh[tid + st]);
        __syncthreads();
    }
    m = sh[0];
    __syncthreads();
    float s = 0.f;
    for (int j = tid; j < Vn; j += 256) s += expf(p[j] - m);
    sh[tid] = s; __syncthreads();
    for (int st = 128; st > 0; st >>= 1) {
        if (tid < st) sh[tid] += sh[tid + st];
        __syncthreads();
    }
    if (tid == 0) {
        float lse = m + logf(sh[0]);
        g_rowloss[row] = lse - p[targets[row]];
    }
}

__global__ void k_lossreduce(float* __restrict__ out) {
    int tid = threadIdx.x;
    float s = 0.f;
    for (int i = tid; i < Mrows; i += 256) s += g_rowloss[i];
    __shared__ float sh[256];
    sh[tid] = s; __syncthreads();
    for (int st = 128; st > 0; st >>= 1) {
        if (tid < st) sh[tid] += sh[tid + st];
        __syncthreads();
    }
    if (tid == 0) out[0] = sh[0] * (1.f / Mrows);
}

// ---------------- launch --------------------------------------------------------
extern "C" void kernel_launch(void* const* d_in, const int* in_sizes, int n_in,
                              void* d_out, int out_size) {
    const int*   idx     = (const int*)  d_in[0];
    const int*   targets = (const int*)  d_in[1];
    const float* wte     = (const float*)d_in[2];
    const float* wpe     = (const float*)d_in[3];
    const float* ln1_g   = (const float*)d_in[4];
    const float* ln1_b   = (const float*)d_in[5];
    const float* attn_w  = (const float*)d_in[6];
    const float* attn_b  = (const float*)d_in[7];
    const float* proj_w  = (const float*)d_in[8];
    const float* proj_b  = (const float*)d_in[9];
    const float* ln2_g   = (const float*)d_in[10];
    const float* ln2_b   = (const float*)d_in[11];
    const float* fc_w    = (const float*)d_in[12];
    const float* fc_b    = (const float*)d_in[13];
    const float* fc2_w   = (const float*)d_in[14];
    const float* fc2_b   = (const float*)d_in[15];
    const float* lnf_g   = (const float*)d_in[16];
    const float* lnf_b   = (const float*)d_in[17];
    const float* lm_w    = (const float*)d_in[18];
    float* logits = (float*)d_out;

    float *px, *ph, *pqkv, *py, *pfc;
    cudaGetSymbolAddress((void**)&px,   g_x);
    cudaGetSymbolAddress((void**)&ph,   g_h);
    cudaGetSymbolAddress((void**)&pqkv, g_qkv);
    cudaGetSymbolAddress((void**)&py,   g_y);
    cudaGetSymbolAddress((void**)&pfc,  g_fc);

    cudaFuncSetAttribute(k_gemm_mma, cudaFuncAttributeMaxDynamicSharedMemorySize, GEMM_SMEM);
    cudaFuncSetAttribute(k_flash,    cudaFuncAttributeMaxDynamicSharedMemorySize, FA_SMEM);

    k_embed<<<Mrows, 256>>>(idx, wte, wpe);

    for (int l = 0; l < Ln; l++) {
        // attention
        k_ln<<<Mrows, 256>>>(px, ph, ln1_g + (size_t)l * En, ln1_b + (size_t)l * En);
        k_gemm_mma<<<dim3(Mrows / 128, E3 / 128), 256, GEMM_SMEM>>>(
            ph, attn_w + (size_t)l * E3 * En, attn_b + (size_t)l * E3, nullptr,
            pqkv, Mrows, E3, En, 0);
        k_flash<<<dim3(Tn / 64, Bn * Hn), 128, FA_SMEM>>>();
        k_gemm_mma<<<dim3(Mrows / 128, En / 128), 256, GEMM_SMEM>>>(
            py, proj_w + (size_t)l * En * En, proj_b + (size_t)l * En, px,
            px, Mrows, En, En, 0);
        // mlp
        k_ln<<<Mrows, 256>>>(px, ph, ln2_g + (size_t)l * En, ln2_b + (size_t)l * En);
        k_gemm_mma<<<dim3(Mrows / 128, E4 / 128), 256, GEMM_SMEM>>>(
            ph, fc_w + (size_t)l * E4 * En, fc_b + (size_t)l * E4, nullptr,
            pfc, Mrows, E4, En, 1);
        k_gemm_mma<<<dim3(Mrows / 128, En / 128), 256, GEMM_SMEM>>>(
            pfc, fc2_w + (size_t)l * En * E4, fc2_b + (size_t)l * En, px,
            px, Mrows, En, E4, 0);
    }

    // final ln + lm head + loss
    k_ln<<<Mrows, 256>>>(px, ph, lnf_g, lnf_b);
    k_gemm_mma<<<dim3(Mrows / 128, Vn / 128), 256, GEMM_SMEM>>>(
        ph, lm_w, nullptr, nullptr, logits, Mrows, Vn, En, 0);
    k_lossrow<<<Mrows, 256>>>(logits, targets);
    k_lossreduce<<<1, 256>>>(logits + (size_t)Mrows * Vn);
}